// round 1
// baseline (speedup 1.0000x reference)
#include <cuda_runtime.h>
#include <stdint.h>
#include <math.h>

#define BATCH   8
#define NANCH   76725
#define NC      80
#define NF      84
#define KMAX    100
#define CAP     4096
#define NPAIR   (BATCH*NC)
#define FLOOR_LOGIT 2.0f
#define SCORE_TH 0.05f
#define IOU_THR 0.5f

// -------- scratch (device globals; no allocations allowed) --------
__device__ float g_boxes[BATCH*NANCH*4];      // decoded corners
__device__ int   g_cnt[NPAIR];
__device__ float g_cval[NPAIR*CAP];
__device__ int   g_cidx[NPAIR*CAP];
__device__ float g_cls_scores[NPAIR*KMAX];
__device__ float g_cls_boxes[NPAIR*KMAX*4];

__device__ __forceinline__ float sigmoidf_(float x){ return 1.0f/(1.0f+expf(-x)); }
__device__ __forceinline__ unsigned flip_f(unsigned u){ return (u & 0x80000000u) ? ~u : (u | 0x80000000u); }

__global__ void k_init(){
    int t = blockIdx.x*blockDim.x + threadIdx.x;
    if (t < NPAIR) g_cnt[t] = 0;
}

// anchor (computed analytically, numpy-double dims then cast, like reference) + decode
__device__ __forceinline__ float4 decode_anchor_box(int n, float4 bp){
    int off, fw, stride, lvl;
    if      (n < 57600){lvl=0; off=0;     fw=80; stride=8;  }
    else if (n < 72000){lvl=1; off=57600; fw=40; stride=16; }
    else if (n < 75600){lvl=2; off=72000; fw=20; stride=32; }
    else if (n < 76500){lvl=3; off=75600; fw=10; stride=64; }
    else               {lvl=4; off=76500; fw=5;  stride=128;}
    int local = n - off;
    int k = local % 9;
    int cell = local / 9;
    int j = cell % fw, i = cell / fw;
    double side = 32.0 * (double)(1 << lvl);
    double area = side * side;
    int ri = k / 3, si = k % 3;
    double ratio = (ri==0) ? 0.5 : ((ri==1) ? 1.0 : 2.0);
    double scale = (si==0) ? 1.0 : ((si==1) ? 1.2599210498948732 : 1.5874010519681994);
    double ah = sqrt(area / ratio);
    double aw = area / ah;
    float w = (float)(scale * aw);
    float h = (float)(scale * ah);
    float cx = ((float)j + 0.5f) * (float)stride;
    float cy = ((float)i + 0.5f) * (float)stride;
    float x  = bp.x * 0.1f * w + cx;
    float y  = bp.y * 0.1f * h + cy;
    float ww = expf(bp.z * 0.2f) * w;
    float hh = expf(bp.w * 0.2f) * h;
    float4 o;
    o.x = x - ww*0.5f; o.y = y - hh*0.5f;
    o.z = x + ww*0.5f; o.w = y + hh*0.5f;
    return o;
}

// single coalesced sweep: decode boxes + collect class candidates above floor
__global__ __launch_bounds__(256) void k_collect(const float* __restrict__ pred){
    const int total4 = BATCH*NANCH*(NF/4);   // 12,889,800 float4s
    for (int e = blockIdx.x*blockDim.x + threadIdx.x; e < total4; e += gridDim.x*blockDim.x){
        float4 v = __ldg(((const float4*)pred) + e);
        int row = e / 21;                 // b*NANCH + n
        int c0  = (e - row*21) * 4;
        int b   = row / NANCH;
        int n   = row - b*NANCH;
        if (c0 == 0){
            ((float4*)g_boxes)[row] = decode_anchor_box(n, v);
        } else {
            int pbase = b*NC + (c0 - 4);
            float vv[4] = {v.x, v.y, v.z, v.w};
            #pragma unroll
            for (int q = 0; q < 4; q++){
                if (vv[q] > FLOOR_LOGIT){
                    int p = pbase + q;
                    int slot = atomicAdd(&g_cnt[p], 1);
                    if (slot < CAP){ g_cval[p*CAP+slot] = vv[q]; g_cidx[p*CAP+slot] = n; }
                }
            }
        }
    }
}

// exact fallback: only runs for pairs with <KMAX or >CAP candidates (never on this data)
__global__ __launch_bounds__(256) void k_fallback(const float* __restrict__ pred){
    const int p = blockIdx.x;
    int cnt = g_cnt[p];
    if (cnt >= KMAX && cnt <= CAP) return;
    const int tid = threadIdx.x;
    const int b = p / NC, c = p % NC;
    const float* base = pred + (size_t)b*NANCH*NF + 4 + c;
    __shared__ int s_cnt;
    if (tid == 0) s_cnt = 0;
    __syncthreads();
    int loc = 0;
    for (int n = tid; n < NANCH; n += blockDim.x){
        float v = base[(size_t)n*NF];
        if (sigmoidf_(v) > SCORE_TH) loc++;
    }
    atomicAdd(&s_cnt, loc);
    __syncthreads();
    const int total = s_cnt;
    const int T = min(total, KMAX);
    if (T == 0){ if (tid == 0) g_cnt[p] = 0; return; }
    unsigned long long lo = 0ull, hi = ~0ull;
    while (lo < hi){
        unsigned long long mid = lo + ((hi - lo) >> 1) + 1ull;
        __syncthreads();
        if (tid == 0) s_cnt = 0;
        __syncthreads();
        int cc = 0;
        for (int n = tid; n < NANCH; n += blockDim.x){
            float v = base[(size_t)n*NF];
            if (sigmoidf_(v) > SCORE_TH){
                unsigned u = flip_f(__float_as_uint(v));
                unsigned long long kk = ((unsigned long long)u << 32) | (unsigned)(0x7FFFFFFF - n);
                if (kk >= mid) cc++;
            }
        }
        atomicAdd(&s_cnt, cc);
        __syncthreads();
        if (s_cnt >= T) lo = mid; else hi = mid - 1;
    }
    __syncthreads();
    if (tid == 0) s_cnt = 0;
    __syncthreads();
    for (int n = tid; n < NANCH; n += blockDim.x){
        float v = base[(size_t)n*NF];
        if (sigmoidf_(v) > SCORE_TH){
            unsigned u = flip_f(__float_as_uint(v));
            unsigned long long kk = ((unsigned long long)u << 32) | (unsigned)(0x7FFFFFFF - n);
            if (kk >= lo){
                int sl = atomicAdd(&s_cnt, 1);
                if (sl < CAP){ g_cval[p*CAP+sl] = v; g_cidx[p*CAP+sl] = n; }
            }
        }
    }
    __syncthreads();
    if (tid == 0) g_cnt[p] = T;
}

__device__ __forceinline__ void bitonic128_desc(unsigned long long* s_key, int tid){
    for (int k = 2; k <= 128; k <<= 1){
        for (int j = k >> 1; j > 0; j >>= 1){
            if (tid < 128){
                int ixj = tid ^ j;
                if (ixj > tid){
                    unsigned long long a = s_key[tid], bb = s_key[ixj];
                    bool desc = ((tid & k) == 0);
                    bool sw = desc ? (a < bb) : (a > bb);
                    if (sw){ s_key[tid] = bb; s_key[ixj] = a; }
                }
            }
            __syncthreads();
        }
    }
}

// per (image,class): exact top-100 (score desc, index asc tie-break) + greedy NMS
__global__ __launch_bounds__(512) void k_classnms(){
    const int p = blockIdx.x;
    const int tid = threadIdx.x;
    int cnt = g_cnt[p]; if (cnt > CAP) cnt = CAP;
    const int T = min(cnt, KMAX);

    unsigned long long key[8];
    #pragma unroll
    for (int q = 0; q < 8; q++){
        int s = tid + q*512;
        unsigned long long kk = 0ull;
        if (s < cnt){
            float sc = sigmoidf_(g_cval[p*CAP+s]);   // positive -> bits are order-preserving
            int n = g_cidx[p*CAP+s];
            kk = ((unsigned long long)__float_as_uint(sc) << 32) | (unsigned)(0x7FFFFFFF - n);
        }
        key[q] = kk;
    }

    __shared__ int s_count, s_n;
    __shared__ unsigned long long s_key[128];
    unsigned long long lo = 0ull, hi = ~0ull;
    if (T > 0){
        while (lo < hi){
            unsigned long long mid = lo + ((hi - lo) >> 1) + 1ull;
            __syncthreads();
            if (tid == 0) s_count = 0;
            __syncthreads();
            int c = 0;
            #pragma unroll
            for (int q = 0; q < 8; q++) c += (key[q] >= mid);
            for (int o = 16; o; o >>= 1) c += __shfl_down_sync(0xFFFFFFFFu, c, o);
            if ((tid & 31) == 0 && c) atomicAdd(&s_count, c);
            __syncthreads();
            if (s_count >= T) lo = mid; else hi = mid - 1;
        }
    }
    __syncthreads();
    if (tid == 0) s_n = 0;
    if (tid < 128) s_key[tid] = 0ull;
    __syncthreads();
    if (T > 0){
        #pragma unroll
        for (int q = 0; q < 8; q++){
            if (key[q] >= lo && key[q] != 0ull){
                int pos = atomicAdd(&s_n, 1);
                if (pos < 128) s_key[pos] = key[q];
            }
        }
    }
    __syncthreads();
    bitonic128_desc(s_key, tid);

    __shared__ float sb0[KMAX], sb1[KMAX], sb2[KMAX], sb3[KMAX], ssc[KMAX];
    __shared__ unsigned char skp[KMAX];
    const int bimg = p / NC;
    if (tid < KMAX){
        unsigned long long kk = s_key[tid];
        float sc = -1.0f; float4 bx = make_float4(0,0,0,0); unsigned char kp = 0;
        if (tid < T && kk != 0ull){
            sc = __uint_as_float((unsigned)(kk >> 32));
            int n = 0x7FFFFFFF - (unsigned)(kk & 0xFFFFFFFFull);
            bx = ((const float4*)g_boxes)[bimg*NANCH + n];
            kp = 1;   // sc = sigmoid > 0, matches keep init (sk > 0)
        }
        sb0[tid]=bx.x; sb1[tid]=bx.y; sb2[tid]=bx.z; sb3[tid]=bx.w;
        ssc[tid]=sc; skp[tid]=kp;
    }
    __syncthreads();

    // exact greedy NMS, mirroring the reference fori_loop
    for (int i = 0; i < KMAX; i++){
        if (skp[i] && tid < KMAX && tid > i && skp[tid]){
            float ax=sb0[i], ay=sb1[i], az=sb2[i], aw=sb3[i];
            float ltx = fmaxf(ax, sb0[tid]), lty = fmaxf(ay, sb1[tid]);
            float rbx = fminf(az, sb2[tid]), rby = fminf(aw, sb3[tid]);
            float w = fmaxf(rbx - ltx, 0.0f), h = fmaxf(rby - lty, 0.0f);
            float inter = w*h;
            float a1 = (az-ax)*(aw-ay);
            float a2 = (sb2[tid]-sb0[tid])*(sb3[tid]-sb1[tid]);
            float iou = inter / (a1 + a2 - inter + 1e-8f);
            if (iou > IOU_THR) skp[tid] = 0;
        }
        __syncthreads();
    }

    if (tid < KMAX){
        g_cls_scores[p*KMAX + tid] = skp[tid] ? ssc[tid] : -1.0f;
        ((float4*)g_cls_boxes)[p*KMAX + tid] = make_float4(sb0[tid], sb1[tid], sb2[tid], sb3[tid]);
    }
}

// per image: top-100 of 8000 candidates, write final outputs
__global__ __launch_bounds__(1024) void k_merge(float* __restrict__ out){
    const int b = blockIdx.x;
    const int tid = threadIdx.x;
    const int M = NC*KMAX;  // 8000

    unsigned long long key[8];
    #pragma unroll
    for (int q = 0; q < 8; q++){
        int s = tid + q*1024;
        unsigned long long kk = 0ull;
        if (s < M){
            float sc = g_cls_scores[b*M + s];
            unsigned u = flip_f(__float_as_uint(sc));
            kk = ((unsigned long long)u << 32) | (unsigned)(0x7FFFFFFF - s);
        }
        key[q] = kk;
    }

    __shared__ int s_count, s_n, s_valid;
    __shared__ unsigned long long s_key[128];
    const int T = KMAX;
    unsigned long long lo = 0ull, hi = ~0ull;
    while (lo < hi){
        unsigned long long mid = lo + ((hi - lo) >> 1) + 1ull;
        __syncthreads();
        if (tid == 0) s_count = 0;
        __syncthreads();
        int c = 0;
        #pragma unroll
        for (int q = 0; q < 8; q++) c += (key[q] >= mid);
        for (int o = 16; o; o >>= 1) c += __shfl_down_sync(0xFFFFFFFFu, c, o);
        if ((tid & 31) == 0 && c) atomicAdd(&s_count, c);
        __syncthreads();
        if (s_count >= T) lo = mid; else hi = mid - 1;
    }
    __syncthreads();
    if (tid == 0){ s_n = 0; s_valid = 0; }
    if (tid < 128) s_key[tid] = 0ull;
    __syncthreads();
    #pragma unroll
    for (int q = 0; q < 8; q++){
        if (key[q] >= lo && key[q] != 0ull){
            int pos = atomicAdd(&s_n, 1);
            if (pos < 128) s_key[pos] = key[q];
        }
    }
    __syncthreads();
    bitonic128_desc(s_key, tid);

    if (tid < KMAX){
        unsigned long long kk = s_key[tid];
        unsigned u = (unsigned)(kk >> 32);
        float sc = __uint_as_float((u & 0x80000000u) ? (u & 0x7FFFFFFFu) : ~u);
        int s = 0x7FFFFFFF - (unsigned)(kk & 0xFFFFFFFFull);
        bool good = sc > 0.0f;
        float4 bx = make_float4(0,0,0,0);
        float clsf = 0.0f;
        if (good){
            bx = ((const float4*)g_cls_boxes)[b*M + s];
            clsf = (float)(s / KMAX);
            atomicAdd(&s_valid, 1);
        }
        ((float4*)out)[b*KMAX + tid] = bx;                       // boxes  [0, 3200)
        out[BATCH*KMAX*4 + b*KMAX + tid] = fmaxf(sc, 0.0f);      // scores [3200, 4000)
        out[BATCH*KMAX*5 + b*KMAX + tid] = clsf;                 // classes[4000, 4800)
    }
    __syncthreads();
    if (tid == 0) out[BATCH*KMAX*6 + b] = (float)s_valid;        // valid  [4800, 4808)
}

extern "C" void kernel_launch(void* const* d_in, const int* in_sizes, int n_in,
                              void* d_out, int out_size){
    // locate predictions input by element count (8*76725*84)
    const float* pred = nullptr;
    const int PRED_SZ = BATCH*NANCH*NF;
    int best = -1;
    for (int i = 0; i < n_in; i++){
        if (in_sizes[i] == PRED_SZ){ pred = (const float*)d_in[i]; break; }
        if (best < 0 || in_sizes[i] > in_sizes[best]) best = i;
    }
    if (!pred) pred = (const float*)d_in[best < 0 ? 0 : best];

    float* out = (float*)d_out;
    (void)out_size;

    k_init<<<(NPAIR + 255)/256, 256>>>();
    k_collect<<<2048, 256>>>(pred);
    k_fallback<<<NPAIR, 256>>>(pred);
    k_classnms<<<NPAIR, 512>>>();
    k_merge<<<BATCH, 1024>>>(out);
}

// round 2
// speedup vs baseline: 2.0262x; 2.0262x over previous
#include <cuda_runtime.h>
#include <stdint.h>
#include <math.h>

#define BATCH   8
#define NANCH   76725
#define NROWS   (BATCH*NANCH)
#define NC      80
#define NF      84
#define KMAX    100
#define CAP     4096
#define NPAIR   (BATCH*NC)
#define FLOOR_LOGIT 2.0f
#define SCORE_TH 0.05f
#define IOU_THR 0.5f
#define CSH     5   // g_cnt stride = 32 ints = 128B (spread atomics across L2 slices)

typedef unsigned long long u64;
typedef unsigned int u32;

// -------- scratch (device globals; no allocations allowed) --------
__device__ float4 g_anchors[NANCH];
__device__ float  g_boxes[NROWS*4];
__device__ int    g_cnt[NPAIR<<CSH];
__device__ u64    g_cand[NPAIR*CAP];            // packed (sigmoid_bits<<32)|(0x7FFFFFFF-n)
__device__ float  g_cls_scores[NPAIR*KMAX];
__device__ float  g_cls_boxes[NPAIR*KMAX*4];

__device__ __forceinline__ float sigmoidf_(float x){ return 1.0f/(1.0f+expf(-x)); }
__device__ __forceinline__ u32 flip_f(u32 u){ return (u & 0x80000000u) ? ~u : (u | 0x80000000u); }

// ---------------- init: anchors (double math, once) + counter reset ----------------
__global__ void k_init(){
    int t = blockIdx.x*blockDim.x + threadIdx.x;
    if (t < NPAIR) g_cnt[t<<CSH] = 0;
    if (t >= NANCH) return;
    int n = t;
    int off, fw, stride, lvl;
    if      (n < 57600){lvl=0; off=0;     fw=80; stride=8;  }
    else if (n < 72000){lvl=1; off=57600; fw=40; stride=16; }
    else if (n < 75600){lvl=2; off=72000; fw=20; stride=32; }
    else if (n < 76500){lvl=3; off=75600; fw=10; stride=64; }
    else               {lvl=4; off=76500; fw=5;  stride=128;}
    int local = n - off;
    int k = local % 9;
    int cell = local / 9;
    int j = cell % fw, i = cell / fw;
    double side = 32.0 * (double)(1 << lvl);
    double area = side * side;
    int ri = k / 3, si = k % 3;
    double ratio = (ri==0) ? 0.5 : ((ri==1) ? 1.0 : 2.0);
    double scale = (si==0) ? 1.0 : ((si==1) ? 1.2599210498948732 : 1.5874010519681994);
    double ah = sqrt(area / ratio);
    double aw = area / ah;
    float4 a;
    a.x = ((float)j + 0.5f) * (float)stride;   // cx
    a.y = ((float)i + 0.5f) * (float)stride;   // cy
    a.z = (float)(scale * aw);                 // w
    a.w = (float)(scale * ah);                 // h
    g_anchors[n] = a;
}

// ---------------- decode boxes (float-only, anchors from table) ----------------
__global__ __launch_bounds__(256) void k_boxes(const float4* __restrict__ pred4){
    int row = blockIdx.x*blockDim.x + threadIdx.x;
    if (row >= NROWS) return;
    int n = row % NANCH;
    float4 bp = __ldg(pred4 + row*21);
    float4 a  = g_anchors[n];
    float x  = (bp.x*0.1f)*a.z + a.x;
    float y  = (bp.y*0.1f)*a.w + a.y;
    float ww = expf(bp.z*0.2f)*a.z;
    float hh = expf(bp.w*0.2f)*a.w;
    ((float4*)g_boxes)[row] = make_float4(x - ww*0.5f, y - hh*0.5f, x + ww*0.5f, y + hh*0.5f);
}

// ---------------- class sweep: zero index math in hot loop ----------------
// total threads MUST be a multiple of 20 -> per-thread residue r is loop-invariant.
__global__ __launch_bounds__(256) void k_scan(const float4* __restrict__ pred4){
    const int S = gridDim.x*blockDim.x;          // multiple of 20
    const int t = blockIdx.x*blockDim.x + threadIdx.x;
    const int r = (t % 20) + 1;                  // chunk index 1..20 within row
    int row = t / 20;
    const int drow = S / 20;
    const int cbase = (r<<2) - 4;                // class base for this thread
    int b = 0; int n = row;
    while (n >= NANCH){ n -= NANCH; b++; }
    const float4* ptr = pred4 + row*21 + r;
    const int step = drow*21;
    #pragma unroll 4
    for (; row < NROWS; row += drow){
        float4 v = __ldg(ptr);
        float m = fmaxf(fmaxf(v.x, v.y), fmaxf(v.z, v.w));
        if (m > FLOOR_LOGIT){
            float vv[4] = {v.x, v.y, v.z, v.w};
            #pragma unroll
            for (int q = 0; q < 4; q++){
                if (vv[q] > FLOOR_LOGIT){
                    int p = b*NC + cbase + q;
                    int slot = atomicAdd(&g_cnt[p<<CSH], 1);
                    if (slot < CAP){
                        float sc = sigmoidf_(vv[q]);
                        g_cand[p*CAP + slot] = ((u64)__float_as_uint(sc)<<32) | (u32)(0x7FFFFFFF - n);
                    }
                }
            }
        }
        ptr += step;
        n += drow;
        if (n >= NANCH){ n -= NANCH; b++; }
    }
}

// ---------------- exact fallback (only for <KMAX or >CAP candidates; never on this data) ----------------
__global__ __launch_bounds__(256) void k_fallback(const float* __restrict__ pred){
    const int p = blockIdx.x;
    int cnt = g_cnt[p<<CSH];
    if (cnt >= KMAX && cnt <= CAP) return;
    const int tid = threadIdx.x;
    const int b = p / NC, c = p % NC;
    const float* base = pred + (size_t)b*NANCH*NF + 4 + c;
    __shared__ int s_cnt;
    if (tid == 0) s_cnt = 0;
    __syncthreads();
    int loc = 0;
    for (int n = tid; n < NANCH; n += 256){
        if (sigmoidf_(base[(size_t)n*NF]) > SCORE_TH) loc++;
    }
    atomicAdd(&s_cnt, loc);
    __syncthreads();
    const int total = s_cnt;
    const int T = min(total, KMAX);
    if (T == 0){ if (tid == 0) g_cnt[p<<CSH] = 0; return; }
    u64 lo = 0ull, hi = ~0ull;
    while (lo < hi){
        u64 mid = lo + ((hi - lo) >> 1) + 1ull;
        __syncthreads();
        if (tid == 0) s_cnt = 0;
        __syncthreads();
        int cc = 0;
        for (int n = tid; n < NANCH; n += 256){
            float sc = sigmoidf_(base[(size_t)n*NF]);
            if (sc > SCORE_TH){
                u64 kk = ((u64)__float_as_uint(sc)<<32) | (u32)(0x7FFFFFFF - n);
                if (kk >= mid) cc++;
            }
        }
        atomicAdd(&s_cnt, cc);
        __syncthreads();
        if (s_cnt >= T) lo = mid; else hi = mid - 1;
    }
    __syncthreads();
    if (tid == 0) s_cnt = 0;
    __syncthreads();
    for (int n = tid; n < NANCH; n += 256){
        float sc = sigmoidf_(base[(size_t)n*NF]);
        if (sc > SCORE_TH){
            u64 kk = ((u64)__float_as_uint(sc)<<32) | (u32)(0x7FFFFFFF - n);
            if (kk >= lo){
                int sl = atomicAdd(&s_cnt, 1);
                if (sl < CAP) g_cand[p*CAP + sl] = kk;
            }
        }
    }
    __syncthreads();
    if (tid == 0) g_cnt[p<<CSH] = T;
}

// ---------------- radix top-k threshold (8-bit digits, match_any histogram) ----------------
__device__ __forceinline__ void hist_add(int* bins, int digit, bool act){
    int lane = threadIdx.x & 31;
    int v = act ? digit : (512 + lane);               // distinct sentinels for inactive lanes
    unsigned m = __match_any_sync(0xFFFFFFFFu, v);
    if (act && ((m & ((1u<<lane)-1u)) == 0))          // lowest lane in equal-digit group
        atomicAdd(&bins[digit], __popc(m));
}

template<int KPT>
__device__ u64 radix_topk_threshold(const u64* key, int need0, int* bins, u64* sh_pref, int* sh_need){
    const int tid = threadIdx.x;
    u64 prefix = 0; int need = need0;
    for (int pass = 0; pass < 8; pass++){
        int shift = 56 - (pass<<3);
        bins[tid] = 0;
        __syncthreads();
        #pragma unroll
        for (int q = 0; q < KPT; q++){
            u64 k = key[q];
            bool act;
            if (pass == 0) act = (k != 0ull);
            else           act = (k != 0ull) && ((k >> (shift+8)) == prefix);
            hist_add(bins, (int)((k >> shift) & 255), act);
        }
        __syncthreads();
        if (tid < 32){
            int c[8]; int lsum = 0;
            #pragma unroll
            for (int j = 0; j < 8; j++){ c[j] = bins[(tid<<3)+j]; lsum += c[j]; }
            int acc = lsum;
            #pragma unroll
            for (int off = 1; off < 32; off <<= 1){
                int t2 = __shfl_down_sync(0xFFFFFFFFu, acc, off);
                if (tid + off < 32) acc += t2;
            }
            int cum = acc - lsum;                     // count in lanes above me
            #pragma unroll
            for (int j = 7; j >= 0; j--){
                int nx = cum + c[j];
                if (cum < need && need <= nx){
                    *sh_pref = (prefix << 8) | (u64)((tid<<3) + j);
                    *sh_need = need - cum;
                }
                cum = nx;
            }
        }
        __syncthreads();
        prefix = *sh_pref; need = *sh_need;
        __syncthreads();
    }
    return prefix;  // exact need0-th largest key (keys are distinct)
}

// ---------------- per (image,class): top-100 + greedy NMS via suppression masks ----------------
__global__ __launch_bounds__(256) void k_classnms(){
    const int p = blockIdx.x;
    const int tid = threadIdx.x;
    int cnt = g_cnt[p<<CSH]; if (cnt > CAP) cnt = CAP;
    const int T = min(cnt, KMAX);
    const int bimg = p / NC;

    u64 key[16];
    #pragma unroll
    for (int q = 0; q < 16; q++){
        int s = tid + (q<<8);
        key[q] = (s < cnt) ? g_cand[p*CAP + s] : 0ull;
    }

    __shared__ int bins[256];
    __shared__ u64 sh_pref; __shared__ int sh_need;
    __shared__ int s_n;
    __shared__ u64 s_key[128];
    __shared__ float ssc[128], sb0[128], sb1[128], sb2[128], sb3[128];
    __shared__ u64 sup0[KMAX], sup1[KMAX];
    __shared__ u64 s_keep0, s_keep1;

    u64 thr = ~0ull;
    if (T > 0) thr = radix_topk_threshold<16>(key, T, bins, &sh_pref, &sh_need);

    if (tid == 0) s_n = 0;
    if (tid < 128){ s_key[tid] = 0ull; ssc[tid] = -1.0f; sb0[tid]=0.f; sb1[tid]=0.f; sb2[tid]=0.f; sb3[tid]=0.f; }
    __syncthreads();
    if (T > 0){
        #pragma unroll
        for (int q = 0; q < 16; q++){
            u64 k = key[q];
            if (k != 0ull && k >= thr){
                int pos = atomicAdd(&s_n, 1);
                if (pos < 128) s_key[pos] = k;
            }
        }
    }
    __syncthreads();
    // rank placement (keys distinct)
    if (tid < T){
        u64 k = s_key[tid];
        int rank = 0;
        for (int j = 0; j < T; j++) rank += (s_key[j] > k);
        float sc = __uint_as_float((u32)(k >> 32));
        int n = 0x7FFFFFFF - (int)(u32)(k & 0xFFFFFFFFull);
        float4 bx = ((const float4*)g_boxes)[bimg*NANCH + n];
        ssc[rank] = sc; sb0[rank]=bx.x; sb1[rank]=bx.y; sb2[rank]=bx.z; sb3[rank]=bx.w;
    }
    __syncthreads();
    // suppression mask matrix (j > i only)
    if (tid < T){
        u64 m0 = 0ull, m1 = 0ull;
        float ax=sb0[tid], ay=sb1[tid], az=sb2[tid], aw=sb3[tid];
        float a1 = (az-ax)*(aw-ay);
        for (int j = tid+1; j < T; j++){
            float ltx = fmaxf(ax, sb0[j]), lty = fmaxf(ay, sb1[j]);
            float rbx = fminf(az, sb2[j]), rby = fminf(aw, sb3[j]);
            float w = fmaxf(rbx - ltx, 0.0f), h = fmaxf(rby - lty, 0.0f);
            float inter = w*h;
            float a2 = (sb2[j]-sb0[j])*(sb3[j]-sb1[j]);
            float iou = inter / (a1 + a2 - inter + 1e-8f);
            if (iou > IOU_THR){ if (j < 64) m0 |= (1ull<<j); else m1 |= (1ull<<(j-64)); }
        }
        sup0[tid] = m0; sup1[tid] = m1;
    }
    __syncthreads();
    // sequential greedy on bitmasks (exact reference semantics)
    if (tid == 0){
        u64 k0, k1;
        if (T >= 64){ k0 = ~0ull; k1 = (T == 64) ? 0ull : ((1ull << (T-64)) - 1ull); }
        else        { k0 = (T == 0) ? 0ull : ((1ull << T) - 1ull); k1 = 0ull; }
        for (int i = 0; i < T; i++){
            bool kept = (i < 64) ? ((k0 >> i) & 1ull) : ((k1 >> (i-64)) & 1ull);
            if (kept){ k0 &= ~sup0[i]; k1 &= ~sup1[i]; }
        }
        s_keep0 = k0; s_keep1 = k1;
    }
    __syncthreads();
    if (tid < KMAX){
        bool kept = (tid < T) && ((tid < 64) ? ((s_keep0 >> tid) & 1ull) : ((s_keep1 >> (tid-64)) & 1ull));
        g_cls_scores[p*KMAX + tid] = kept ? ssc[tid] : -1.0f;
        ((float4*)g_cls_boxes)[p*KMAX + tid] = make_float4(sb0[tid], sb1[tid], sb2[tid], sb3[tid]);
    }
}

// ---------------- per image merge: top-100 of 8000, write outputs ----------------
__global__ __launch_bounds__(256) void k_merge(float* __restrict__ out){
    const int b = blockIdx.x;
    const int tid = threadIdx.x;
    const int M = NC*KMAX;  // 8000

    u64 key[32];
    #pragma unroll
    for (int q = 0; q < 32; q++){
        int s = tid + (q<<8);
        u64 kk = 0ull;
        if (s < M){
            float sc = g_cls_scores[b*M + s];
            u32 u = flip_f(__float_as_uint(sc));
            kk = ((u64)u << 32) | (u32)(0x7FFFFFFF - s);
        }
        key[q] = kk;
    }

    __shared__ int bins[256];
    __shared__ u64 sh_pref; __shared__ int sh_need;
    __shared__ int s_n, s_valid;
    __shared__ u64 s_key[128];
    __shared__ u64 s_sorted[128];

    u64 thr = radix_topk_threshold<32>(key, KMAX, bins, &sh_pref, &sh_need);

    if (tid == 0){ s_n = 0; s_valid = 0; }
    if (tid < 128){ s_key[tid] = 0ull; s_sorted[tid] = 0ull; }
    __syncthreads();
    #pragma unroll
    for (int q = 0; q < 32; q++){
        u64 k = key[q];
        if (k != 0ull && k >= thr){
            int pos = atomicAdd(&s_n, 1);
            if (pos < 128) s_key[pos] = k;
        }
    }
    __syncthreads();
    if (tid < KMAX){
        u64 k = s_key[tid];
        int rank = 0;
        for (int j = 0; j < KMAX; j++) rank += (s_key[j] > k);
        s_sorted[rank] = k;
    }
    __syncthreads();
    if (tid < KMAX){
        u64 k = s_sorted[tid];
        u32 u = (u32)(k >> 32);
        float sc = __uint_as_float((u & 0x80000000u) ? (u & 0x7FFFFFFFu) : ~u);
        int s = 0x7FFFFFFF - (int)(u32)(k & 0xFFFFFFFFull);
        bool good = sc > 0.0f;
        float4 bx = make_float4(0,0,0,0); float clsf = 0.0f;
        if (good){
            bx = ((const float4*)g_cls_boxes)[b*M + s];
            clsf = (float)(s / KMAX);
            atomicAdd(&s_valid, 1);
        }
        ((float4*)out)[b*KMAX + tid] = bx;                       // boxes  [0, 3200)
        out[BATCH*KMAX*4 + b*KMAX + tid] = fmaxf(sc, 0.0f);      // scores [3200, 4000)
        out[BATCH*KMAX*5 + b*KMAX + tid] = clsf;                 // classes[4000, 4800)
    }
    __syncthreads();
    if (tid == 0) out[BATCH*KMAX*6 + b] = (float)s_valid;        // valid  [4800, 4808)
}

extern "C" void kernel_launch(void* const* d_in, const int* in_sizes, int n_in,
                              void* d_out, int out_size){
    const float* pred = nullptr;
    const int PRED_SZ = BATCH*NANCH*NF;
    int best = -1;
    for (int i = 0; i < n_in; i++){
        if (in_sizes[i] == PRED_SZ){ pred = (const float*)d_in[i]; break; }
        if (best < 0 || in_sizes[i] > in_sizes[best]) best = i;
    }
    if (!pred) pred = (const float*)d_in[best < 0 ? 0 : best];

    float* out = (float*)d_out;
    (void)out_size;

    k_init<<<(NANCH + 255)/256, 256>>>();
    k_boxes<<<(NROWS + 255)/256, 256>>>((const float4*)pred);
    k_scan<<<640, 256>>>((const float4*)pred);      // 640*256 = 163840 ≡ 0 (mod 20)
    k_fallback<<<NPAIR, 256>>>(pred);
    k_classnms<<<NPAIR, 256>>>();
    k_merge<<<BATCH, 256>>>(out);
}

// round 3
// speedup vs baseline: 4.0985x; 2.0227x over previous
#include <cuda_runtime.h>
#include <stdint.h>
#include <math.h>

#define BATCH   8
#define NANCH   76725
#define NROWS   (BATCH*NANCH)
#define NC      80
#define NF      84
#define KMAX    100
#define CAP     1024
#define NPAIR   (BATCH*NC)
#define FLOOR_LOGIT 2.5f
#define SCORE_TH 0.05f
#define IOU_THR 0.5f
#define CSH     5   // g_cnt stride = 32 ints = 128B

typedef unsigned long long u64;
typedef unsigned int u32;

// -------- scratch (device globals) --------
__device__ float2 g_dims[45];                 // 45 distinct anchor (w,h), double-exact
__device__ float  g_boxes[NROWS*4];           // decoded corners
__device__ int    g_cnt[NPAIR<<CSH];
__device__ u64    g_cand[NPAIR*CAP];          // (flip(logit)<<32) | (0x7FFFFFFF - n)
__device__ float  g_cls_scores[NPAIR*KMAX];
__device__ float  g_cls_boxes[NPAIR*KMAX*4];

__device__ __forceinline__ float sigmoidf_(float x){ return 1.0f/(1.0f+expf(-x)); }
__device__ __forceinline__ u32 flip_f(u32 u){ return (u & 0x80000000u) ? ~u : (u | 0x80000000u); }
__device__ __forceinline__ float unflip_f(u32 u){
    return __uint_as_float((u & 0x80000000u) ? (u ^ 0x80000000u) : ~u);
}

// ---------------- tiny init: 45 dims (only FP64 in the program) + counter reset ----------------
__global__ void k_dims(){
    int t = blockIdx.x*blockDim.x + threadIdx.x;
    if (t < NPAIR) g_cnt[t<<CSH] = 0;
    if (t < 45){
        int lvl = t/9, k = t%9, ri = k/3, si = k%3;
        double side = 32.0 * (double)(1 << lvl);
        double area = side*side;
        double ratio = (ri==0) ? 0.5 : ((ri==1) ? 1.0 : 2.0);
        double scale = (si==0) ? 1.0 : ((si==1) ? 1.2599210498948732 : 1.5874010519681994);
        double ah = sqrt(area / ratio);
        double aw = area / ah;
        g_dims[t] = make_float2((float)(scale*aw), (float)(scale*ah));
    }
}

// ---------------- fused sweep: decode boxes (r==0 lanes) + collect candidates (r=1..20) ----------------
// total threads MUST be a multiple of 21.
__global__ __launch_bounds__(256) void k_sweep(const float4* __restrict__ pred4){
    const int S = gridDim.x*blockDim.x;        // multiple of 21
    const int t = blockIdx.x*blockDim.x + threadIdx.x;
    const int r = t % 21;                      // 0 = box chunk, 1..20 = class chunks
    int row = t / 21;
    const int drow = S / 21;
    const int cbase = (r<<2) - 4;
    int b = 0, n = row;                        // drow < NANCH, row0 < NANCH
    const float4* ptr = pred4 + row*21 + r;
    const int step = drow*21;
    #pragma unroll 2
    for (; row < NROWS; row += drow){
        float4 v = __ldg(ptr);
        if (r == 0){
            int lvl = (n>=57600) + (n>=72000) + (n>=75600) + (n>=76500);
            int off = (lvl==0)?0 : (lvl==1)?57600 : (lvl==2)?72000 : (lvl==3)?75600 : 76500;
            int local = n - off;
            int k9   = local % 9;
            int cell = local / 9;
            int sh = 4 - lvl;                  // fw = 5 << sh
            int i = (cell/5) >> sh;
            int j = cell - i*(5<<sh);
            float stridef = (float)(8<<lvl);
            float2 d = g_dims[lvl*9 + k9];
            float cx = ((float)j + 0.5f) * stridef;
            float cy = ((float)i + 0.5f) * stridef;
            float x  = (v.x*0.1f)*d.x + cx;
            float y  = (v.y*0.1f)*d.y + cy;
            float ww = expf(v.z*0.2f)*d.x;
            float hh = expf(v.w*0.2f)*d.y;
            ((float4*)g_boxes)[row] = make_float4(x - ww*0.5f, y - hh*0.5f, x + ww*0.5f, y + hh*0.5f);
        } else {
            float m = fmaxf(fmaxf(v.x, v.y), fmaxf(v.z, v.w));
            if (m > FLOOR_LOGIT){
                float vv[4] = {v.x, v.y, v.z, v.w};
                #pragma unroll
                for (int q = 0; q < 4; q++){
                    if (vv[q] > FLOOR_LOGIT){
                        int p = b*NC + cbase + q;
                        int slot = atomicAdd(&g_cnt[p<<CSH], 1);
                        if (slot < CAP)
                            g_cand[p*CAP + slot] =
                                ((u64)(__float_as_uint(vv[q]) | 0x80000000u) << 32) | (u32)(0x7FFFFFFF - n);
                    }
                }
            }
        }
        ptr += step;
        n += drow;
        if (n >= NANCH){ n -= NANCH; b++; }
    }
}

// ---------------- exact fallback (only for <KMAX or >CAP candidates; never on this data) ----------------
__global__ __launch_bounds__(256) void k_fallback(const float* __restrict__ pred){
    const int p = blockIdx.x;
    int cnt = g_cnt[p<<CSH];
    if (cnt >= KMAX && cnt <= CAP) return;
    const int tid = threadIdx.x;
    const int b = p / NC, c = p % NC;
    const float* base = pred + (size_t)b*NANCH*NF + 4 + c;
    __shared__ int s_cnt;
    if (tid == 0) s_cnt = 0;
    __syncthreads();
    int loc = 0;
    for (int n = tid; n < NANCH; n += 256){
        if (sigmoidf_(base[(size_t)n*NF]) > SCORE_TH) loc++;
    }
    atomicAdd(&s_cnt, loc);
    __syncthreads();
    const int total = s_cnt;
    const int T = min(total, KMAX);
    if (T == 0){ if (tid == 0) g_cnt[p<<CSH] = 0; return; }
    u64 lo = 0ull, hi = ~0ull;
    while (lo < hi){
        u64 mid = lo + ((hi - lo) >> 1) + 1ull;
        __syncthreads();
        if (tid == 0) s_cnt = 0;
        __syncthreads();
        int cc = 0;
        for (int n = tid; n < NANCH; n += 256){
            float v = base[(size_t)n*NF];
            if (sigmoidf_(v) > SCORE_TH){
                u64 kk = ((u64)flip_f(__float_as_uint(v)) << 32) | (u32)(0x7FFFFFFF - n);
                if (kk >= mid) cc++;
            }
        }
        atomicAdd(&s_cnt, cc);
        __syncthreads();
        if (s_cnt >= T) lo = mid; else hi = mid - 1;
    }
    __syncthreads();
    if (tid == 0) s_cnt = 0;
    __syncthreads();
    for (int n = tid; n < NANCH; n += 256){
        float v = base[(size_t)n*NF];
        if (sigmoidf_(v) > SCORE_TH){
            u64 kk = ((u64)flip_f(__float_as_uint(v)) << 32) | (u32)(0x7FFFFFFF - n);
            if (kk >= lo){
                int sl = atomicAdd(&s_cnt, 1);
                if (sl < CAP) g_cand[p*CAP + sl] = kk;
            }
        }
    }
    __syncthreads();
    if (tid == 0) g_cnt[p<<CSH] = T;
}

// ---------------- radix top-k threshold (8-bit digits, match_any histogram) ----------------
__device__ __forceinline__ void hist_add(int* bins, int digit, bool act){
    int lane = threadIdx.x & 31;
    int v = act ? digit : (512 + lane);
    unsigned m = __match_any_sync(0xFFFFFFFFu, v);
    if (act && ((m & ((1u<<lane)-1u)) == 0))
        atomicAdd(&bins[digit], __popc(m));
}

template<int KPT>
__device__ u64 radix_topk_threshold(const u64* key, int need0, int* bins, u64* sh_pref, int* sh_need){
    const int tid = threadIdx.x;
    u64 prefix = 0; int need = need0;
    for (int pass = 0; pass < 8; pass++){
        int shift = 56 - (pass<<3);
        bins[tid] = 0;
        __syncthreads();
        #pragma unroll
        for (int q = 0; q < KPT; q++){
            u64 k = key[q];
            bool act;
            if (pass == 0) act = (k != 0ull);
            else           act = (k != 0ull) && ((k >> (shift+8)) == prefix);
            hist_add(bins, (int)((k >> shift) & 255), act);
        }
        __syncthreads();
        if (tid < 32){
            int c[8]; int lsum = 0;
            #pragma unroll
            for (int j = 0; j < 8; j++){ c[j] = bins[(tid<<3)+j]; lsum += c[j]; }
            int acc = lsum;
            #pragma unroll
            for (int off = 1; off < 32; off <<= 1){
                int t2 = __shfl_down_sync(0xFFFFFFFFu, acc, off);
                if (tid + off < 32) acc += t2;
            }
            int cum = acc - lsum;
            #pragma unroll
            for (int j = 7; j >= 0; j--){
                int nx = cum + c[j];
                if (cum < need && need <= nx){
                    *sh_pref = (prefix << 8) | (u64)((tid<<3) + j);
                    *sh_need = need - cum;
                }
                cum = nx;
            }
        }
        __syncthreads();
        prefix = *sh_pref; need = *sh_need;
        __syncthreads();
    }
    return prefix;
}

// ---------------- per (image,class): top-100 + greedy NMS via suppression masks ----------------
__global__ __launch_bounds__(256) void k_classnms(){
    const int p = blockIdx.x;
    const int tid = threadIdx.x;
    int cnt = g_cnt[p<<CSH]; if (cnt > CAP) cnt = CAP;
    const int T = min(cnt, KMAX);
    const int bimg = p / NC;

    u64 key[4];
    #pragma unroll
    for (int q = 0; q < 4; q++){
        int s = tid + (q<<8);
        key[q] = (s < cnt) ? g_cand[p*CAP + s] : 0ull;
    }

    __shared__ int bins[256];
    __shared__ u64 sh_pref; __shared__ int sh_need;
    __shared__ int s_n;
    __shared__ u64 s_key[128];
    __shared__ float ssc[128], sb0[128], sb1[128], sb2[128], sb3[128];
    __shared__ u64 sup0[KMAX], sup1[KMAX];
    __shared__ u64 s_keep0, s_keep1;

    u64 thr = ~0ull;
    if (T > 0) thr = radix_topk_threshold<4>(key, T, bins, &sh_pref, &sh_need);

    if (tid == 0) s_n = 0;
    if (tid < 128){ s_key[tid] = 0ull; ssc[tid] = -1.0f; sb0[tid]=0.f; sb1[tid]=0.f; sb2[tid]=0.f; sb3[tid]=0.f; }
    __syncthreads();
    if (T > 0){
        #pragma unroll
        for (int q = 0; q < 4; q++){
            u64 k = key[q];
            if (k != 0ull && k >= thr){
                int pos = atomicAdd(&s_n, 1);
                if (pos < 128) s_key[pos] = k;
            }
        }
    }
    __syncthreads();
    if (tid < T){
        u64 k = s_key[tid];
        int rank = 0;
        for (int j = 0; j < T; j++) rank += (s_key[j] > k);
        float logit = unflip_f((u32)(k >> 32));
        float sc = sigmoidf_(logit);
        int n = 0x7FFFFFFF - (int)(u32)(k & 0xFFFFFFFFull);
        float4 bx = ((const float4*)g_boxes)[bimg*NANCH + n];
        ssc[rank] = sc; sb0[rank]=bx.x; sb1[rank]=bx.y; sb2[rank]=bx.z; sb3[rank]=bx.w;
    }
    __syncthreads();
    if (tid < T){
        u64 m0 = 0ull, m1 = 0ull;
        float ax=sb0[tid], ay=sb1[tid], az=sb2[tid], aw=sb3[tid];
        float a1 = (az-ax)*(aw-ay);
        for (int j = tid+1; j < T; j++){
            float ltx = fmaxf(ax, sb0[j]), lty = fmaxf(ay, sb1[j]);
            float rbx = fminf(az, sb2[j]), rby = fminf(aw, sb3[j]);
            float w = fmaxf(rbx - ltx, 0.0f), h = fmaxf(rby - lty, 0.0f);
            float inter = w*h;
            float a2 = (sb2[j]-sb0[j])*(sb3[j]-sb1[j]);
            float iou = inter / (a1 + a2 - inter + 1e-8f);
            if (iou > IOU_THR){ if (j < 64) m0 |= (1ull<<j); else m1 |= (1ull<<(j-64)); }
        }
        sup0[tid] = m0; sup1[tid] = m1;
    }
    __syncthreads();
    if (tid == 0){
        u64 k0, k1;
        if (T >= 64){ k0 = ~0ull; k1 = (T == 64) ? 0ull : ((1ull << (T-64)) - 1ull); }
        else        { k0 = (T == 0) ? 0ull : ((1ull << T) - 1ull); k1 = 0ull; }
        for (int i = 0; i < T; i++){
            bool kept = (i < 64) ? ((k0 >> i) & 1ull) : ((k1 >> (i-64)) & 1ull);
            if (kept){ k0 &= ~sup0[i]; k1 &= ~sup1[i]; }
        }
        s_keep0 = k0; s_keep1 = k1;
    }
    __syncthreads();
    if (tid < KMAX){
        bool kept = (tid < T) && ((tid < 64) ? ((s_keep0 >> tid) & 1ull) : ((s_keep1 >> (tid-64)) & 1ull));
        g_cls_scores[p*KMAX + tid] = kept ? ssc[tid] : -1.0f;
        ((float4*)g_cls_boxes)[p*KMAX + tid] = make_float4(sb0[tid], sb1[tid], sb2[tid], sb3[tid]);
    }
}

// ---------------- per image merge: top-100 of 8000, write outputs ----------------
__global__ __launch_bounds__(256) void k_merge(float* __restrict__ out){
    const int b = blockIdx.x;
    const int tid = threadIdx.x;
    const int M = NC*KMAX;

    u64 key[32];
    #pragma unroll
    for (int q = 0; q < 32; q++){
        int s = tid + (q<<8);
        u64 kk = 0ull;
        if (s < M){
            float sc = g_cls_scores[b*M + s];
            kk = ((u64)flip_f(__float_as_uint(sc)) << 32) | (u32)(0x7FFFFFFF - s);
        }
        key[q] = kk;
    }

    __shared__ int bins[256];
    __shared__ u64 sh_pref; __shared__ int sh_need;
    __shared__ int s_n, s_valid;
    __shared__ u64 s_key[128];
    __shared__ u64 s_sorted[128];

    u64 thr = radix_topk_threshold<32>(key, KMAX, bins, &sh_pref, &sh_need);

    if (tid == 0){ s_n = 0; s_valid = 0; }
    if (tid < 128){ s_key[tid] = 0ull; s_sorted[tid] = 0ull; }
    __syncthreads();
    #pragma unroll
    for (int q = 0; q < 32; q++){
        u64 k = key[q];
        if (k != 0ull && k >= thr){
            int pos = atomicAdd(&s_n, 1);
            if (pos < 128) s_key[pos] = k;
        }
    }
    __syncthreads();
    if (tid < KMAX){
        u64 k = s_key[tid];
        int rank = 0;
        for (int j = 0; j < KMAX; j++) rank += (s_key[j] > k);
        s_sorted[rank] = k;
    }
    __syncthreads();
    if (tid < KMAX){
        u64 k = s_sorted[tid];
        float sc = unflip_f((u32)(k >> 32));
        int s = 0x7FFFFFFF - (int)(u32)(k & 0xFFFFFFFFull);
        bool good = sc > 0.0f;
        float4 bx = make_float4(0,0,0,0); float clsf = 0.0f;
        if (good){
            bx = ((const float4*)g_cls_boxes)[b*M + s];
            clsf = (float)(s / KMAX);
            atomicAdd(&s_valid, 1);
        }
        ((float4*)out)[b*KMAX + tid] = bx;
        out[BATCH*KMAX*4 + b*KMAX + tid] = fmaxf(sc, 0.0f);
        out[BATCH*KMAX*5 + b*KMAX + tid] = clsf;
    }
    __syncthreads();
    if (tid == 0) out[BATCH*KMAX*6 + b] = (float)s_valid;
}

extern "C" void kernel_launch(void* const* d_in, const int* in_sizes, int n_in,
                              void* d_out, int out_size){
    const float* pred = nullptr;
    const int PRED_SZ = BATCH*NANCH*NF;
    int best = -1;
    for (int i = 0; i < n_in; i++){
        if (in_sizes[i] == PRED_SZ){ pred = (const float*)d_in[i]; break; }
        if (best < 0 || in_sizes[i] > in_sizes[best]) best = i;
    }
    if (!pred) pred = (const float*)d_in[best < 0 ? 0 : best];

    float* out = (float*)d_out;
    (void)out_size;

    k_dims<<<(NPAIR + 255)/256, 256>>>();
    k_sweep<<<1344, 256>>>((const float4*)pred);    // 1344*256 = 344064 = 21*16384
    k_fallback<<<NPAIR, 256>>>(pred);
    k_classnms<<<NPAIR, 256>>>();
    k_merge<<<BATCH, 256>>>(out);
}